// round 9
// baseline (speedup 1.0000x reference)
#include <cuda_runtime.h>
#include <cstddef>

#define FFT_N 8192
#define NT    1024
#define CH    64

// XOR swizzle on float2 index: conflict-free (<=2-way worst case) for all
// access patterns used here.
#define SWZ(a) ((a) ^ (((a) >> 4) & 15))

__device__ __forceinline__ float2 cmul(float2 a, float2 b) {
    return make_float2(fmaf(a.x, b.x, -a.y * b.y), fmaf(a.x, b.y, a.y * b.x));
}
__device__ __forceinline__ float2 cadd(float2 a, float2 b) { return make_float2(a.x + b.x, a.y + b.y); }
__device__ __forceinline__ float2 csub(float2 a, float2 b) { return make_float2(a.x - b.x, a.y - b.y); }

template<int DIR>
__device__ __forceinline__ void dft4(float2& a, float2& b, float2& c, float2& d) {
    float2 t0 = cadd(a, c), t1 = csub(a, c);
    float2 t2 = cadd(b, d), t3 = csub(b, d);
    a = cadd(t0, t2);
    c = csub(t0, t2);
    if (DIR > 0) {
        b = make_float2(t1.x + t3.y, t1.y - t3.x);
        d = make_float2(t1.x - t3.y, t1.y + t3.x);
    } else {
        b = make_float2(t1.x - t3.y, t1.y + t3.x);
        d = make_float2(t1.x + t3.y, t1.y - t3.x);
    }
}

// In-place DFT8, natural-order outputs.
template<int DIR>
__device__ __forceinline__ void dft8(float2 v[8]) {
    dft4<DIR>(v[0], v[2], v[4], v[6]);
    dft4<DIR>(v[1], v[3], v[5], v[7]);
    const float C2 = 0.70710678118654752f;
    const float s  = (DIR > 0) ? 1.0f : -1.0f;
    v[3] = cmul(v[3], make_float2( C2, -s * C2));
    v[5] = cmul(v[5], make_float2(0.f, -s      ));
    v[7] = cmul(v[7], make_float2(-C2, -s * C2));
    float2 y[8];
    #pragma unroll
    for (int k2 = 0; k2 < 4; k2++) {
        y[k2]     = cadd(v[2 * k2], v[2 * k2 + 1]);
        y[k2 + 4] = csub(v[2 * k2], v[2 * k2 + 1]);
    }
    #pragma unroll
    for (int o = 0; o < 8; o++) v[o] = y[o];
}

// In-place DFT16 (two radix-4 levels). Output X[k2+4*k1] lives in slot
// 4*k2+k1; callers permute on store: slot(o) = ((o&3)<<2)|(o>>2).
template<int DIR>
__device__ __forceinline__ void dft16(float2 v[16]) {
    #pragma unroll
    for (int n1 = 0; n1 < 4; n1++)
        dft4<DIR>(v[n1], v[n1 + 4], v[n1 + 8], v[n1 + 12]);
    const float C1 = 0.92387953251128674f;   // cos(2pi/16)
    const float S1 = 0.38268343236508978f;   // sin(2pi/16)
    const float C2 = 0.70710678118654752f;
    const float s  = (DIR > 0) ? 1.0f : -1.0f;
    v[5]  = cmul(v[5],  make_float2( C1, -s * S1));
    v[6]  = cmul(v[6],  make_float2( C2, -s * C2));
    v[7]  = cmul(v[7],  make_float2( S1, -s * C1));
    v[9]  = cmul(v[9],  make_float2( C2, -s * C2));
    v[10] = cmul(v[10], make_float2(0.f, -s      ));
    v[11] = cmul(v[11], make_float2(-C2, -s * C2));
    v[13] = cmul(v[13], make_float2( S1, -s * C1));
    v[14] = cmul(v[14], make_float2(-C2, -s * C2));
    v[15] = cmul(v[15], make_float2(-C1,  s * S1));
    #pragma unroll
    for (int k2 = 0; k2 < 4; k2++)
        dft4<DIR>(v[4 * k2], v[4 * k2 + 1], v[4 * k2 + 2], v[4 * k2 + 3]);
}

template<int S, int DIR>
__device__ __forceinline__ void stage_read(const float2* __restrict__ buf, int j,
                                           float2 w1, float2 v[8]) {
    #pragma unroll
    for (int r = 0; r < 8; r++)
        v[r] = buf[SWZ(j + r * (FFT_N / 8))];
    if (S > 1) {
        float2 w = w1;
        #pragma unroll
        for (int r = 1; r < 8; r++) {
            v[r] = cmul(v[r], w);
            if (r < 7) w = cmul(w, w1);
        }
    }
    dft8<DIR>(v);
}

template<int S>
__device__ __forceinline__ void stage_write(float2* __restrict__ buf, int j,
                                            const float2 v[8]) {
    const int jq   = j & (S - 1);
    const int base = jq + (j / S) * (S * 8);
    #pragma unroll
    for (int o = 0; o < 8; o++)
        buf[SWZ(base + S * o)] = v[o];
}

// One in-place radix-8 stage applied to both buffers, interleaved:
// read0 | bar | write0+read1 | bar | write1 | bar. Guarded per pair.
template<int S, int DIR>
__device__ __forceinline__ void stage_pair(float2* b0, float2* b1, int j,
                                           bool p0, bool p1) {
    float2 w1 = make_float2(1.f, 0.f);
    if (S > 1) {
        float ss, cc;
        sincospif((DIR > 0 ? -2.0f : 2.0f) * (float)(j & (S - 1)) / (8.0f * (float)S), &ss, &cc);
        w1 = make_float2(cc, ss);
    }
    float2 v[8];
    if (p0) stage_read<S, DIR>(b0, j, w1, v);
    __syncthreads();
    if (p0) stage_write<S>(b0, j, v);
    if (p1) stage_read<S, DIR>(b1, j, w1, v);
    __syncthreads();
    if (p1) stage_write<S>(b1, j, v);
    __syncthreads();
}

// Hermitian rebuild for one (ka, kb=(N-ka)%N) pair of one buffer:
// unpack packed FFT Z into per-channel amplitudes, apply random phases,
// re-symmetrize into W = H_A + i*H_B. Writes W in place.
__device__ __forceinline__ void rebuild(float2* __restrict__ buf, int ka, int kb,
                                        float2 phA, float2 phB) {
    const float TWO_PI = 6.283185307179586476925f;
    const float scale  = 0.25f / (float)FFT_N;
    float2 Za = buf[SWZ(ka)], Zb = buf[SWZ(kb)];
    float ax = Za.x + Zb.x, ay = Za.y - Zb.y;
    float bx = Za.y + Zb.y, by = Zb.x - Za.x;
    float ampA = sqrtf(fmaf(ax, ax, ay * ay)) * scale;
    float ampB = sqrtf(fmaf(bx, bx, by * by)) * scale;
    float sA1, cA1, sA2, cA2, sB1, cB1, sB2, cB2;
    __sincosf(TWO_PI * phA.x, &sA1, &cA1);
    __sincosf(TWO_PI * phA.y, &sA2, &cA2);
    __sincosf(TWO_PI * phB.x, &sB1, &cB1);
    __sincosf(TWO_PI * phB.y, &sB2, &cB2);
    float h1x = ampA * (cA1 + cA2), h1y = ampA * (sA1 - sA2);
    float h2x = ampB * (cB1 + cB2), h2y = ampB * (sB1 - sB2);
    buf[SWZ(ka)] = make_float2(h1x - h2y, h1y + h2x);
    buf[SWZ(kb)] = make_float2(h1x + h2y, h2x - h1y);
}

__global__ __launch_bounds__(NT, 1)
void surrogate_kernel(const float* __restrict__ wave,
                      const float* __restrict__ phases,
                      const float* __restrict__ mask,
                      float* __restrict__ out) {
    const int blk = blockIdx.x;
    const int b   = blk >> 4;
    const int c0  = (blk & 15) * 4;
    const int tid = threadIdx.x;

    const bool s0 = mask[b * CH + c0]     < 0.5f;
    const bool s1 = mask[b * CH + c0 + 1] < 0.5f;
    const bool s2 = mask[b * CH + c0 + 2] < 0.5f;
    const bool s3 = mask[b * CH + c0 + 3] < 0.5f;
    const bool p0 = s0 | s1;
    const bool p1 = s2 | s3;

    const float4* w4 = (const float4*)(wave   + (size_t)b * FFT_N * CH + c0);
    const float4* p4 = (const float4*)(phases + (size_t)b * FFT_N * CH + c0);
    float4*       o4 = (float4*)      (out    + (size_t)b * FFT_N * CH + c0);

    if (!p0 && !p1) {
        #pragma unroll 4
        for (int t = tid; t < FFT_N; t += NT)
            o4[(size_t)t * 16] = w4[(size_t)t * 16];
        return;
    }

    extern __shared__ float2 sm[];
    float2* b0 = sm;                        // pair 0: ch c0 + i*ch(c0+1)
    float2* b1 = sm + FFT_N;                // pair 1: ch c0+2 + i*ch(c0+3)
    float4* P  = (float4*)(sm + 2 * FFT_N); // phase rows: [0,2048) and [6144,8192)

    // ---- Load pass + phase prefetch (half 1, consumed ~15K cycles later) --
    #pragma unroll
    for (int i = 0; i < FFT_N / NT; i++) {
        int t = tid + i * NT;
        float4 g = w4[(size_t)t * 16];
        b0[SWZ(t)] = make_float2(g.x, g.y);
        b1[SWZ(t)] = make_float2(g.z, g.w);
    }
    #pragma unroll
    for (int m = 0; m < 4; m++) {
        int i = tid + m * NT;                 // i in [0,4096)
        int r = (i < 2048) ? i : i + 4096;    // rows [0,2048) U [6144,8192)
        P[i] = p4[(size_t)r * 16];
    }
    __syncthreads();

    // ---- Forward FFT: radix-8 x3 (interleaved in place) + radix-16 ---------
    stage_pair<1,  1>(b0, b1, tid, p0, p1);
    stage_pair<8,  1>(b0, b1, tid, p0, p1);
    stage_pair<64, 1>(b0, b1, tid, p0, p1);
    {   // S=512 radix-16: thread-halves map 1:1 onto the two pairs.
        const int   half = tid >> 9;
        const int   j    = tid & 511;
        float2*     buf  = half ? b1 : b0;
        const bool  act  = half ? p1 : p0;
        float2 v[16];
        if (act) {
            #pragma unroll
            for (int r = 0; r < 16; r++)
                v[r] = buf[SWZ(j + r * 512)];
            float ss, cc;
            sincospif(-(float)j / 4096.0f, &ss, &cc);   // w1 = e^{-2pi i j/8192}
            float2 w1 = make_float2(cc, ss);
            float2 w  = w1;
            #pragma unroll
            for (int r = 1; r < 16; r++) {
                v[r] = cmul(v[r], w);
                if (r < 15) w = cmul(w, w1);
            }
            dft16<1>(v);
        }
        __syncthreads();
        if (act) {
            #pragma unroll
            for (int o = 0; o < 16; o++) {
                int slot = ((o & 3) << 2) | (o >> 2);
                buf[SWZ(j + 512 * o)] = v[slot];
            }
        }
        __syncthreads();
    }

    // ---- Spectrum rebuild: half 1 phases from smem P, half 2 from gmem -----
    #pragma unroll
    for (int m = 0; m < 2; m++) {            // k in [0,2048)
        int k  = tid + m * NT;
        int nk = (FFT_N - k) & (FFT_N - 1);
        float4 pk  = P[k];
        float4 pnk = (k == 0) ? P[0] : P[nk - 4096];
        if (p0) rebuild(b0, k, nk, make_float2(pk.x, pnk.x), make_float2(pk.y, pnk.y));
        if (p1) rebuild(b1, k, nk, make_float2(pk.z, pnk.z), make_float2(pk.w, pnk.w));
    }
    #pragma unroll
    for (int m = 2; m < 4; m++) {            // k in [2048,4096)
        int k  = tid + m * NT;
        int nk = FFT_N - k;
        float4 pk  = p4[(size_t)k  * 16];
        float4 pnk = p4[(size_t)nk * 16];
        if (p0) rebuild(b0, k, nk, make_float2(pk.x, pnk.x), make_float2(pk.y, pnk.y));
        if (p1) rebuild(b1, k, nk, make_float2(pk.z, pnk.z), make_float2(pk.w, pnk.w));
    }
    if (tid == 0) {                          // k = 4096 (self-paired)
        float4 pk = p4[(size_t)4096 * 16];
        if (p0) rebuild(b0, 4096, 4096, make_float2(pk.x, pk.x), make_float2(pk.y, pk.y));
        if (p1) rebuild(b1, 4096, 4096, make_float2(pk.z, pk.z), make_float2(pk.w, pk.w));
    }
    __syncthreads();

    // ---- Inverse FFT: radix-8 x4 (interleaved in place) --------------------
    stage_pair<1,   -1>(b0, b1, tid, p0, p1);
    stage_pair<8,   -1>(b0, b1, tid, p0, p1);
    stage_pair<64,  -1>(b0, b1, tid, p0, p1);
    stage_pair<512, -1>(b0, b1, tid, p0, p1);

    // ---- Final inverse radix-2 fused with select + float4 store ------------
    const bool all4 = s0 & s1 & s2 & s3;
    #pragma unroll
    for (int i = 0; i < FFT_N / 2 / NT; i++) {
        int j = tid + i * NT;
        float ss, cc;
        sincospif((float)j / 4096.0f, &ss, &cc);
        float2 w = make_float2(cc, ss);
        float2 y0, y1, z0, z1;
        if (p0) {
            float2 u0 = b0[SWZ(j)], u1 = cmul(b0[SWZ(j + 4096)], w);
            y0 = cadd(u0, u1);  y1 = csub(u0, u1);
        } else {   // pair fully kept: b0 still holds the originals (in place)
            y0 = b0[SWZ(j)];  y1 = b0[SWZ(j + 4096)];
        }
        if (p1) {
            float2 u0 = b1[SWZ(j)], u1 = cmul(b1[SWZ(j + 4096)], w);
            z0 = cadd(u0, u1);  z1 = csub(u0, u1);
        } else {
            z0 = b1[SWZ(j)];  z1 = b1[SWZ(j + 4096)];
        }
        if (all4) {
            o4[(size_t)j * 16]          = make_float4(y0.x, y0.y, z0.x, z0.y);
            o4[(size_t)(j + 4096) * 16] = make_float4(y1.x, y1.y, z1.x, z1.y);
        } else {
            float4 ga = w4[(size_t)j * 16];
            float4 gb = w4[(size_t)(j + 4096) * 16];
            o4[(size_t)j * 16] = make_float4(s0 ? y0.x : ga.x, s1 ? y0.y : ga.y,
                                             s2 ? z0.x : ga.z, s3 ? z0.y : ga.w);
            o4[(size_t)(j + 4096) * 16] = make_float4(s0 ? y1.x : gb.x, s1 ? y1.y : gb.y,
                                                      s2 ? z1.x : gb.z, s3 ? z1.y : gb.w);
        }
    }
}

extern "C" void kernel_launch(void* const* d_in, const int* in_sizes, int n_in,
                              void* d_out, int out_size) {
    const float* wave   = (const float*)d_in[0];
    const float* phases = (const float*)d_in[1];
    const float* maskp  = (const float*)d_in[2];
    float* out = (float*)d_out;

    const int B = in_sizes[0] / (FFT_N * CH);
    const int smem = 2 * FFT_N * (int)sizeof(float2) + 4096 * (int)sizeof(float4); // 196,608 B

    cudaFuncSetAttribute(surrogate_kernel,
                         cudaFuncAttributeMaxDynamicSharedMemorySize, smem);
    surrogate_kernel<<<B * (CH / 4), NT, smem>>>(wave, phases, maskp, out);
}

// round 10
// speedup vs baseline: 1.0939x; 1.0939x over previous
#include <cuda_runtime.h>
#include <cstddef>

#define FFT_N 8192
#define NT    1024
#define CH    64

// XOR swizzle on float2 index: conflict-free (<=2-way worst case) for all
// access patterns used here.
#define SWZ(a) ((a) ^ (((a) >> 4) & 15))

__device__ __forceinline__ float2 cmul(float2 a, float2 b) {
    return make_float2(fmaf(a.x, b.x, -a.y * b.y), fmaf(a.x, b.y, a.y * b.x));
}
__device__ __forceinline__ float2 cadd(float2 a, float2 b) { return make_float2(a.x + b.x, a.y + b.y); }
__device__ __forceinline__ float2 csub(float2 a, float2 b) { return make_float2(a.x - b.x, a.y - b.y); }

template<int DIR>
__device__ __forceinline__ void dft4(float2& a, float2& b, float2& c, float2& d) {
    float2 t0 = cadd(a, c), t1 = csub(a, c);
    float2 t2 = cadd(b, d), t3 = csub(b, d);
    a = cadd(t0, t2);
    c = csub(t0, t2);
    if (DIR > 0) {
        b = make_float2(t1.x + t3.y, t1.y - t3.x);
        d = make_float2(t1.x - t3.y, t1.y + t3.x);
    } else {
        b = make_float2(t1.x - t3.y, t1.y + t3.x);
        d = make_float2(t1.x + t3.y, t1.y - t3.x);
    }
}

// In-place DFT16 (two radix-4 levels). Output X[k2+4*k1] lives in slot
// 4*k2+k1; callers permute on store: slot(o) = ((o&3)<<2)|(o>>2).
template<int DIR>
__device__ __forceinline__ void dft16(float2 v[16]) {
    #pragma unroll
    for (int n1 = 0; n1 < 4; n1++)
        dft4<DIR>(v[n1], v[n1 + 4], v[n1 + 8], v[n1 + 12]);
    const float C1 = 0.92387953251128674f;   // cos(2pi/16)
    const float S1 = 0.38268343236508978f;   // sin(2pi/16)
    const float C2 = 0.70710678118654752f;
    const float s  = (DIR > 0) ? 1.0f : -1.0f;
    v[5]  = cmul(v[5],  make_float2( C1, -s * S1));
    v[6]  = cmul(v[6],  make_float2( C2, -s * C2));
    v[7]  = cmul(v[7],  make_float2( S1, -s * C1));
    v[9]  = cmul(v[9],  make_float2( C2, -s * C2));
    v[10] = cmul(v[10], make_float2(0.f, -s      ));
    v[11] = cmul(v[11], make_float2(-C2, -s * C2));
    v[13] = cmul(v[13], make_float2( S1, -s * C1));
    v[14] = cmul(v[14], make_float2(-C2, -s * C2));
    v[15] = cmul(v[15], make_float2(-C1,  s * S1));
    #pragma unroll
    for (int k2 = 0; k2 < 4; k2++)
        dft4<DIR>(v[4 * k2], v[4 * k2 + 1], v[4 * k2 + 2], v[4 * k2 + 3]);
}

// One in-place radix-16 Stockham DIT stage, half-CTA per pair:
// threads [0,512) -> b0, [512,1024) -> b1. One butterfly per thread.
// v[r] = buf[j + 512 r] * w^(jq r), w = exp(DIR * -2 pi i * jq/(16 S));
// buf[jq + 16 S jp + S o] = DFT16(v)[o].
template<int S, int DIR>
__device__ __forceinline__ void stage16_pair(float2* __restrict__ b0,
                                             float2* __restrict__ b1,
                                             int tid, bool p0, bool p1) {
    const int  half = tid >> 9;
    const int  j    = tid & 511;
    float2*    buf  = half ? b1 : b0;
    const bool act  = half ? p1 : p0;
    float2 v[16];
    if (act) {
        #pragma unroll
        for (int r = 0; r < 16; r++)
            v[r] = buf[SWZ(j + r * 512)];
        if (S > 1) {
            const int jq = j & (S - 1);
            float ss, cc;
            sincospif((DIR > 0 ? -2.0f : 2.0f) * (float)jq / (16.0f * (float)S), &ss, &cc);
            float2 w1 = make_float2(cc, ss);
            float2 w  = w1;
            #pragma unroll
            for (int r = 1; r < 16; r++) {
                v[r] = cmul(v[r], w);
                if (r < 15) w = cmul(w, w1);
            }
        }
        dft16<DIR>(v);
    }
    __syncthreads();
    if (act) {
        const int jq   = j & (S - 1);
        const int base = jq + (j / S) * (S * 16);
        #pragma unroll
        for (int o = 0; o < 16; o++) {
            int slot = ((o & 3) << 2) | (o >> 2);
            buf[SWZ(base + S * o)] = v[slot];
        }
    }
    __syncthreads();
}

// Hermitian rebuild for one (ka, kb=(N-ka)%N) pair of one buffer:
// unpack packed FFT Z into per-channel amplitudes, apply random phases,
// re-symmetrize into W = H_A + i*H_B. Writes W in place.
__device__ __forceinline__ void rebuild(float2* __restrict__ buf, int ka, int kb,
                                        float2 phA, float2 phB) {
    const float TWO_PI = 6.283185307179586476925f;
    const float scale  = 0.25f / (float)FFT_N;
    float2 Za = buf[SWZ(ka)], Zb = buf[SWZ(kb)];
    float ax = Za.x + Zb.x, ay = Za.y - Zb.y;
    float bx = Za.y + Zb.y, by = Zb.x - Za.x;
    float ampA = sqrtf(fmaf(ax, ax, ay * ay)) * scale;
    float ampB = sqrtf(fmaf(bx, bx, by * by)) * scale;
    float sA1, cA1, sA2, cA2, sB1, cB1, sB2, cB2;
    __sincosf(TWO_PI * phA.x, &sA1, &cA1);
    __sincosf(TWO_PI * phA.y, &sA2, &cA2);
    __sincosf(TWO_PI * phB.x, &sB1, &cB1);
    __sincosf(TWO_PI * phB.y, &sB2, &cB2);
    float h1x = ampA * (cA1 + cA2), h1y = ampA * (sA1 - sA2);
    float h2x = ampB * (cB1 + cB2), h2y = ampB * (sB1 - sB2);
    buf[SWZ(ka)] = make_float2(h1x - h2y, h1y + h2x);
    buf[SWZ(kb)] = make_float2(h1x + h2y, h2x - h1y);
}

__global__ __launch_bounds__(NT, 1)
void surrogate_kernel(const float* __restrict__ wave,
                      const float* __restrict__ phases,
                      const float* __restrict__ mask,
                      float* __restrict__ out) {
    const int blk = blockIdx.x;
    const int b   = blk >> 4;
    const int c0  = (blk & 15) * 4;
    const int tid = threadIdx.x;

    const bool s0 = mask[b * CH + c0]     < 0.5f;
    const bool s1 = mask[b * CH + c0 + 1] < 0.5f;
    const bool s2 = mask[b * CH + c0 + 2] < 0.5f;
    const bool s3 = mask[b * CH + c0 + 3] < 0.5f;
    const bool p0 = s0 | s1;
    const bool p1 = s2 | s3;

    const float4* w4 = (const float4*)(wave   + (size_t)b * FFT_N * CH + c0);
    const float4* p4 = (const float4*)(phases + (size_t)b * FFT_N * CH + c0);
    float4*       o4 = (float4*)      (out    + (size_t)b * FFT_N * CH + c0);

    if (!p0 && !p1) {
        #pragma unroll 4
        for (int t = tid; t < FFT_N; t += NT)
            o4[(size_t)t * 16] = w4[(size_t)t * 16];
        return;
    }

    extern __shared__ float2 sm[];
    float2* b0 = sm;            // pair 0: ch c0 + i*ch(c0+1)
    float2* b1 = sm + FFT_N;    // pair 1: ch c0+2 + i*ch(c0+3)

    // ---- Load: one float4 per time sample -> both buffers -----------------
    #pragma unroll
    for (int i = 0; i < FFT_N / NT; i++) {
        int t = tid + i * NT;
        float4 g = w4[(size_t)t * 16];
        b0[SWZ(t)] = make_float2(g.x, g.y);
        b1[SWZ(t)] = make_float2(g.z, g.w);
    }
    __syncthreads();

    // ---- Forward FFT: radix-16 x3 (half-CTA per pair) + radix-2 ------------
    stage16_pair<1,   1>(b0, b1, tid, p0, p1);
    stage16_pair<16,  1>(b0, b1, tid, p0, p1);
    stage16_pair<256, 1>(b0, b1, tid, p0, p1);
    #pragma unroll
    for (int i = 0; i < FFT_N / 2 / NT; i++) {
        int j = tid + i * NT;
        float ss, cc;
        sincospif(-(float)j / 4096.0f, &ss, &cc);
        float2 w = make_float2(cc, ss);
        if (p0) {
            float2 u0 = b0[SWZ(j)], u1 = cmul(b0[SWZ(j + 4096)], w);
            b0[SWZ(j)] = cadd(u0, u1);  b0[SWZ(j + 4096)] = csub(u0, u1);
        }
        if (p1) {
            float2 u0 = b1[SWZ(j)], u1 = cmul(b1[SWZ(j + 4096)], w);
            b1[SWZ(j)] = cadd(u0, u1);  b1[SWZ(j + 4096)] = csub(u0, u1);
        }
    }
    __syncthreads();

    // ---- Spectrum rebuild (in place; thread owns pair (k, nk)) -------------
    for (int k = tid; k <= FFT_N / 2; k += NT) {
        const int nk = (FFT_N - k) & (FFT_N - 1);
        float4 pk  = p4[(size_t)k  * 16];
        float4 pnk = p4[(size_t)nk * 16];
        if (p0) rebuild(b0, k, nk, make_float2(pk.x, pnk.x), make_float2(pk.y, pnk.y));
        if (p1) rebuild(b1, k, nk, make_float2(pk.z, pnk.z), make_float2(pk.w, pnk.w));
    }
    __syncthreads();

    // ---- Inverse FFT: radix-16 x3; final radix-2 fused into the store ------
    stage16_pair<1,   -1>(b0, b1, tid, p0, p1);
    stage16_pair<16,  -1>(b0, b1, tid, p0, p1);
    stage16_pair<256, -1>(b0, b1, tid, p0, p1);

    // ---- Final inverse radix-2 + select + float4 store ----------------------
    const bool all4 = s0 & s1 & s2 & s3;
    #pragma unroll
    for (int i = 0; i < FFT_N / 2 / NT; i++) {
        int j = tid + i * NT;
        float ss, cc;
        sincospif((float)j / 4096.0f, &ss, &cc);
        float2 w = make_float2(cc, ss);
        float2 y0, y1, z0, z1;
        if (p0) {
            float2 u0 = b0[SWZ(j)], u1 = cmul(b0[SWZ(j + 4096)], w);
            y0 = cadd(u0, u1);  y1 = csub(u0, u1);
        } else {   // pair fully kept: b0 still holds the originals (in place)
            y0 = b0[SWZ(j)];  y1 = b0[SWZ(j + 4096)];
        }
        if (p1) {
            float2 u0 = b1[SWZ(j)], u1 = cmul(b1[SWZ(j + 4096)], w);
            z0 = cadd(u0, u1);  z1 = csub(u0, u1);
        } else {
            z0 = b1[SWZ(j)];  z1 = b1[SWZ(j + 4096)];
        }
        if (all4) {
            o4[(size_t)j * 16]          = make_float4(y0.x, y0.y, z0.x, z0.y);
            o4[(size_t)(j + 4096) * 16] = make_float4(y1.x, y1.y, z1.x, z1.y);
        } else {
            float4 ga = w4[(size_t)j * 16];
            float4 gb = w4[(size_t)(j + 4096) * 16];
            o4[(size_t)j * 16] = make_float4(s0 ? y0.x : ga.x, s1 ? y0.y : ga.y,
                                             s2 ? z0.x : ga.z, s3 ? z0.y : ga.w);
            o4[(size_t)(j + 4096) * 16] = make_float4(s0 ? y1.x : gb.x, s1 ? y1.y : gb.y,
                                                      s2 ? z1.x : gb.z, s3 ? z1.y : gb.w);
        }
    }
}

extern "C" void kernel_launch(void* const* d_in, const int* in_sizes, int n_in,
                              void* d_out, int out_size) {
    const float* wave   = (const float*)d_in[0];
    const float* phases = (const float*)d_in[1];
    const float* maskp  = (const float*)d_in[2];
    float* out = (float*)d_out;

    const int B = in_sizes[0] / (FFT_N * CH);
    const int smem = 2 * FFT_N * (int)sizeof(float2);   // 131,072 B

    cudaFuncSetAttribute(surrogate_kernel,
                         cudaFuncAttributeMaxDynamicSharedMemorySize, smem);
    surrogate_kernel<<<B * (CH / 4), NT, smem>>>(wave, phases, maskp, out);
}

// round 11
// speedup vs baseline: 1.0987x; 1.0044x over previous
#include <cuda_runtime.h>
#include <cstddef>

#define FFT_N 8192
#define NT    1024
#define CH    64

// XOR swizzle on float2 index: conflict-free (<=2-way worst case) for all
// access patterns used here.
#define SWZ(a) ((a) ^ (((a) >> 4) & 15))

// Named barrier over one 512-thread half (ids 1 and 2; id 0 = __syncthreads).
// bar.sync carries CTA memory-fence semantics (STS drain) like bar 0.
#define BARH(half) asm volatile("bar.sync %0, %1;" :: "r"(1 + (half)), "r"(512) : "memory")

__device__ __forceinline__ float2 cmul(float2 a, float2 b) {
    return make_float2(fmaf(a.x, b.x, -a.y * b.y), fmaf(a.x, b.y, a.y * b.x));
}
__device__ __forceinline__ float2 cadd(float2 a, float2 b) { return make_float2(a.x + b.x, a.y + b.y); }
__device__ __forceinline__ float2 csub(float2 a, float2 b) { return make_float2(a.x - b.x, a.y - b.y); }

template<int DIR>
__device__ __forceinline__ void dft4(float2& a, float2& b, float2& c, float2& d) {
    float2 t0 = cadd(a, c), t1 = csub(a, c);
    float2 t2 = cadd(b, d), t3 = csub(b, d);
    a = cadd(t0, t2);
    c = csub(t0, t2);
    if (DIR > 0) {
        b = make_float2(t1.x + t3.y, t1.y - t3.x);
        d = make_float2(t1.x - t3.y, t1.y + t3.x);
    } else {
        b = make_float2(t1.x - t3.y, t1.y + t3.x);
        d = make_float2(t1.x + t3.y, t1.y - t3.x);
    }
}

// In-place DFT16 (two radix-4 levels). Output X[k2+4*k1] lives in slot
// 4*k2+k1; callers permute on store: slot(o) = ((o&3)<<2)|(o>>2).
template<int DIR>
__device__ __forceinline__ void dft16(float2 v[16]) {
    #pragma unroll
    for (int n1 = 0; n1 < 4; n1++)
        dft4<DIR>(v[n1], v[n1 + 4], v[n1 + 8], v[n1 + 12]);
    const float C1 = 0.92387953251128674f;   // cos(2pi/16)
    const float S1 = 0.38268343236508978f;   // sin(2pi/16)
    const float C2 = 0.70710678118654752f;
    const float s  = (DIR > 0) ? 1.0f : -1.0f;
    v[5]  = cmul(v[5],  make_float2( C1, -s * S1));
    v[6]  = cmul(v[6],  make_float2( C2, -s * C2));
    v[7]  = cmul(v[7],  make_float2( S1, -s * C1));
    v[9]  = cmul(v[9],  make_float2( C2, -s * C2));
    v[10] = cmul(v[10], make_float2(0.f, -s      ));
    v[11] = cmul(v[11], make_float2(-C2, -s * C2));
    v[13] = cmul(v[13], make_float2( S1, -s * C1));
    v[14] = cmul(v[14], make_float2(-C2, -s * C2));
    v[15] = cmul(v[15], make_float2(-C1,  s * S1));
    #pragma unroll
    for (int k2 = 0; k2 < 4; k2++)
        dft4<DIR>(v[4 * k2], v[4 * k2 + 1], v[4 * k2 + 2], v[4 * k2 + 3]);
}

// One in-place radix-16 Stockham DIT stage, half-CTA per pair:
// threads [0,512) -> b0, [512,1024) -> b1. One butterfly per thread.
// Internal sync is PER-HALF (named barriers): halves never share data here,
// so they are free to slip against each other across stages.
template<int S, int DIR>
__device__ __forceinline__ void stage16_pair(float2* __restrict__ b0,
                                             float2* __restrict__ b1,
                                             int tid, bool p0, bool p1) {
    const int  half = tid >> 9;
    const int  j    = tid & 511;
    float2*    buf  = half ? b1 : b0;
    const bool act  = half ? p1 : p0;
    float2 v[16];
    if (act) {
        #pragma unroll
        for (int r = 0; r < 16; r++)
            v[r] = buf[SWZ(j + r * 512)];
        if (S > 1) {
            const int jq = j & (S - 1);
            float ss, cc;
            sincospif((DIR > 0 ? -2.0f : 2.0f) * (float)jq / (16.0f * (float)S), &ss, &cc);
            float2 w1 = make_float2(cc, ss);
            float2 w  = w1;
            #pragma unroll
            for (int r = 1; r < 16; r++) {
                v[r] = cmul(v[r], w);
                if (r < 15) w = cmul(w, w1);
            }
        }
        dft16<DIR>(v);
    }
    BARH(half);
    if (act) {
        const int jq   = j & (S - 1);
        const int base = jq + (j / S) * (S * 16);
        #pragma unroll
        for (int o = 0; o < 16; o++) {
            int slot = ((o & 3) << 2) | (o >> 2);
            buf[SWZ(base + S * o)] = v[slot];
        }
    }
    BARH(half);
}

// Hermitian rebuild for one (ka, kb=(N-ka)%N) pair of one buffer:
// unpack packed FFT Z into per-channel amplitudes, apply random phases,
// re-symmetrize into W = H_A + i*H_B. Writes W in place.
__device__ __forceinline__ void rebuild(float2* __restrict__ buf, int ka, int kb,
                                        float2 phA, float2 phB) {
    const float TWO_PI = 6.283185307179586476925f;
    const float scale  = 0.25f / (float)FFT_N;
    float2 Za = buf[SWZ(ka)], Zb = buf[SWZ(kb)];
    float ax = Za.x + Zb.x, ay = Za.y - Zb.y;
    float bx = Za.y + Zb.y, by = Zb.x - Za.x;
    float ampA = sqrtf(fmaf(ax, ax, ay * ay)) * scale;
    float ampB = sqrtf(fmaf(bx, bx, by * by)) * scale;
    float sA1, cA1, sA2, cA2, sB1, cB1, sB2, cB2;
    __sincosf(TWO_PI * phA.x, &sA1, &cA1);
    __sincosf(TWO_PI * phA.y, &sA2, &cA2);
    __sincosf(TWO_PI * phB.x, &sB1, &cB1);
    __sincosf(TWO_PI * phB.y, &sB2, &cB2);
    float h1x = ampA * (cA1 + cA2), h1y = ampA * (sA1 - sA2);
    float h2x = ampB * (cB1 + cB2), h2y = ampB * (sB1 - sB2);
    buf[SWZ(ka)] = make_float2(h1x - h2y, h1y + h2x);
    buf[SWZ(kb)] = make_float2(h1x + h2y, h2x - h1y);
}

__global__ __launch_bounds__(NT, 1)
void surrogate_kernel(const float* __restrict__ wave,
                      const float* __restrict__ phases,
                      const float* __restrict__ mask,
                      float* __restrict__ out) {
    const int blk = blockIdx.x;
    const int b   = blk >> 4;
    const int c0  = (blk & 15) * 4;
    const int tid = threadIdx.x;

    const bool s0 = mask[b * CH + c0]     < 0.5f;
    const bool s1 = mask[b * CH + c0 + 1] < 0.5f;
    const bool s2 = mask[b * CH + c0 + 2] < 0.5f;
    const bool s3 = mask[b * CH + c0 + 3] < 0.5f;
    const bool p0 = s0 | s1;
    const bool p1 = s2 | s3;

    const float4* w4 = (const float4*)(wave   + (size_t)b * FFT_N * CH + c0);
    const float4* p4 = (const float4*)(phases + (size_t)b * FFT_N * CH + c0);
    float4*       o4 = (float4*)      (out    + (size_t)b * FFT_N * CH + c0);

    if (!p0 && !p1) {
        #pragma unroll 4
        for (int t = tid; t < FFT_N; t += NT)
            o4[(size_t)t * 16] = w4[(size_t)t * 16];
        return;
    }

    extern __shared__ float2 sm[];
    float2* b0 = sm;            // pair 0: ch c0 + i*ch(c0+1)
    float2* b1 = sm + FFT_N;    // pair 1: ch c0+2 + i*ch(c0+3)

    // ---- Load: one float4 per time sample -> both buffers -----------------
    #pragma unroll
    for (int i = 0; i < FFT_N / NT; i++) {
        int t = tid + i * NT;
        float4 g = w4[(size_t)t * 16];
        b0[SWZ(t)] = make_float2(g.x, g.y);
        b1[SWZ(t)] = make_float2(g.z, g.w);
    }
    __syncthreads();   // both buffers written by all threads -> full join

    // ---- Forward FFT: radix-16 x3, halves decoupled; then radix-2 ----------
    stage16_pair<1,   1>(b0, b1, tid, p0, p1);
    stage16_pair<16,  1>(b0, b1, tid, p0, p1);
    stage16_pair<256, 1>(b0, b1, tid, p0, p1);
    __syncthreads();   // join halves: r2 + rebuild touch both buffers

    #pragma unroll
    for (int i = 0; i < FFT_N / 2 / NT; i++) {
        int j = tid + i * NT;
        float ss, cc;
        sincospif(-(float)j / 4096.0f, &ss, &cc);
        float2 w = make_float2(cc, ss);
        if (p0) {
            float2 u0 = b0[SWZ(j)], u1 = cmul(b0[SWZ(j + 4096)], w);
            b0[SWZ(j)] = cadd(u0, u1);  b0[SWZ(j + 4096)] = csub(u0, u1);
        }
        if (p1) {
            float2 u0 = b1[SWZ(j)], u1 = cmul(b1[SWZ(j + 4096)], w);
            b1[SWZ(j)] = cadd(u0, u1);  b1[SWZ(j + 4096)] = csub(u0, u1);
        }
    }
    __syncthreads();

    // ---- Spectrum rebuild (in place; thread owns pair (k, nk)) -------------
    for (int k = tid; k <= FFT_N / 2; k += NT) {
        const int nk = (FFT_N - k) & (FFT_N - 1);
        float4 pk  = p4[(size_t)k  * 16];
        float4 pnk = p4[(size_t)nk * 16];
        if (p0) rebuild(b0, k, nk, make_float2(pk.x, pnk.x), make_float2(pk.y, pnk.y));
        if (p1) rebuild(b1, k, nk, make_float2(pk.z, pnk.z), make_float2(pk.w, pnk.w));
    }
    __syncthreads();   // halves diverge again below

    // ---- Inverse FFT: radix-16 x3, halves decoupled -------------------------
    stage16_pair<1,   -1>(b0, b1, tid, p0, p1);
    stage16_pair<16,  -1>(b0, b1, tid, p0, p1);
    stage16_pair<256, -1>(b0, b1, tid, p0, p1);
    __syncthreads();   // store pass reads both buffers per thread

    // ---- Final inverse radix-2 + select + float4 store ----------------------
    const bool all4 = s0 & s1 & s2 & s3;
    #pragma unroll
    for (int i = 0; i < FFT_N / 2 / NT; i++) {
        int j = tid + i * NT;
        float ss, cc;
        sincospif((float)j / 4096.0f, &ss, &cc);
        float2 w = make_float2(cc, ss);
        float2 y0, y1, z0, z1;
        if (p0) {
            float2 u0 = b0[SWZ(j)], u1 = cmul(b0[SWZ(j + 4096)], w);
            y0 = cadd(u0, u1);  y1 = csub(u0, u1);
        } else {   // pair fully kept: b0 still holds the originals (in place)
            y0 = b0[SWZ(j)];  y1 = b0[SWZ(j + 4096)];
        }
        if (p1) {
            float2 u0 = b1[SWZ(j)], u1 = cmul(b1[SWZ(j + 4096)], w);
            z0 = cadd(u0, u1);  z1 = csub(u0, u1);
        } else {
            z0 = b1[SWZ(j)];  z1 = b1[SWZ(j + 4096)];
        }
        if (all4) {
            o4[(size_t)j * 16]          = make_float4(y0.x, y0.y, z0.x, z0.y);
            o4[(size_t)(j + 4096) * 16] = make_float4(y1.x, y1.y, z1.x, z1.y);
        } else {
            float4 ga = w4[(size_t)j * 16];
            float4 gb = w4[(size_t)(j + 4096) * 16];
            o4[(size_t)j * 16] = make_float4(s0 ? y0.x : ga.x, s1 ? y0.y : ga.y,
                                             s2 ? z0.x : ga.z, s3 ? z0.y : ga.w);
            o4[(size_t)(j + 4096) * 16] = make_float4(s0 ? y1.x : gb.x, s1 ? y1.y : gb.y,
                                                      s2 ? z1.x : gb.z, s3 ? z1.y : gb.w);
        }
    }
}

extern "C" void kernel_launch(void* const* d_in, const int* in_sizes, int n_in,
                              void* d_out, int out_size) {
    const float* wave   = (const float*)d_in[0];
    const float* phases = (const float*)d_in[1];
    const float* maskp  = (const float*)d_in[2];
    float* out = (float*)d_out;

    const int B = in_sizes[0] / (FFT_N * CH);
    const int smem = 2 * FFT_N * (int)sizeof(float2);   // 131,072 B

    cudaFuncSetAttribute(surrogate_kernel,
                         cudaFuncAttributeMaxDynamicSharedMemorySize, smem);
    surrogate_kernel<<<B * (CH / 4), NT, smem>>>(wave, phases, maskp, out);
}

// round 12
// speedup vs baseline: 1.1752x; 1.0696x over previous
#include <cuda_runtime.h>
#include <cstddef>

#define FFT_N 8192
#define NT    1024
#define CH    64

// XOR swizzle on float2 index: conflict-free (<=2-way worst case) for all
// access patterns used here.
#define SWZ(a) ((a) ^ (((a) >> 4) & 15))

// Named barrier over one 512-thread half (ids 1 and 2; id 0 = __syncthreads).
#define BARH(half) asm volatile("bar.sync %0, %1;" :: "r"(1 + (half)), "r"(512) : "memory")

__device__ __forceinline__ float2 cmul(float2 a, float2 b) {
    return make_float2(fmaf(a.x, b.x, -a.y * b.y), fmaf(a.x, b.y, a.y * b.x));
}
__device__ __forceinline__ float2 cadd(float2 a, float2 b) { return make_float2(a.x + b.x, a.y + b.y); }
__device__ __forceinline__ float2 csub(float2 a, float2 b) { return make_float2(a.x - b.x, a.y - b.y); }

template<int DIR>
__device__ __forceinline__ void dft4(float2& a, float2& b, float2& c, float2& d) {
    float2 t0 = cadd(a, c), t1 = csub(a, c);
    float2 t2 = cadd(b, d), t3 = csub(b, d);
    a = cadd(t0, t2);
    c = csub(t0, t2);
    if (DIR > 0) {
        b = make_float2(t1.x + t3.y, t1.y - t3.x);
        d = make_float2(t1.x - t3.y, t1.y + t3.x);
    } else {
        b = make_float2(t1.x - t3.y, t1.y + t3.x);
        d = make_float2(t1.x + t3.y, t1.y - t3.x);
    }
}

// In-place DFT16 (two radix-4 levels). Output X[k2+4*k1] lives in slot
// 4*k2+k1; callers permute on store: slot(o) = ((o&3)<<2)|(o>>2).
template<int DIR>
__device__ __forceinline__ void dft16(float2 v[16]) {
    #pragma unroll
    for (int n1 = 0; n1 < 4; n1++)
        dft4<DIR>(v[n1], v[n1 + 4], v[n1 + 8], v[n1 + 12]);
    const float C1 = 0.92387953251128674f;   // cos(2pi/16)
    const float S1 = 0.38268343236508978f;   // sin(2pi/16)
    const float C2 = 0.70710678118654752f;
    const float s  = (DIR > 0) ? 1.0f : -1.0f;
    v[5]  = cmul(v[5],  make_float2( C1, -s * S1));
    v[6]  = cmul(v[6],  make_float2( C2, -s * C2));
    v[7]  = cmul(v[7],  make_float2( S1, -s * C1));
    v[9]  = cmul(v[9],  make_float2( C2, -s * C2));
    v[10] = cmul(v[10], make_float2(0.f, -s      ));
    v[11] = cmul(v[11], make_float2(-C2, -s * C2));
    v[13] = cmul(v[13], make_float2( S1, -s * C1));
    v[14] = cmul(v[14], make_float2(-C2, -s * C2));
    v[15] = cmul(v[15], make_float2(-C1,  s * S1));
    #pragma unroll
    for (int k2 = 0; k2 < 4; k2++)
        dft4<DIR>(v[4 * k2], v[4 * k2 + 1], v[4 * k2 + 2], v[4 * k2 + 3]);
}

// One in-place radix-16 Stockham DIT stage, half-CTA per pair:
// threads [0,512) -> b0, [512,1024) -> b1. One butterfly per thread.
// Internal sync is PER-HALF (named barriers).
template<int S, int DIR>
__device__ __forceinline__ void stage16_pair(float2* __restrict__ b0,
                                             float2* __restrict__ b1,
                                             int tid, bool p0, bool p1) {
    const int  half = tid >> 9;
    const int  j    = tid & 511;
    float2*    buf  = half ? b1 : b0;
    const bool act  = half ? p1 : p0;
    float2 v[16];
    if (act) {
        #pragma unroll
        for (int r = 0; r < 16; r++)
            v[r] = buf[SWZ(j + r * 512)];
        if (S > 1) {
            const int jq = j & (S - 1);
            float ss, cc;
            sincospif((DIR > 0 ? -2.0f : 2.0f) * (float)jq / (16.0f * (float)S), &ss, &cc);
            float2 w1 = make_float2(cc, ss);
            float2 w  = w1;
            #pragma unroll
            for (int r = 1; r < 16; r++) {
                v[r] = cmul(v[r], w);
                if (r < 15) w = cmul(w, w1);
            }
        }
        dft16<DIR>(v);
    }
    BARH(half);
    if (act) {
        const int jq   = j & (S - 1);
        const int base = jq + (j / S) * (S * 16);
        #pragma unroll
        for (int o = 0; o < 16; o++) {
            int slot = ((o & 3) << 2) | (o >> 2);
            buf[SWZ(base + S * o)] = v[slot];
        }
    }
    BARH(half);
}

// Hermitian rebuild for one (ka, kb=(N-ka)%N) pair of one buffer.
// For a SURROGATE channel: amplitude from the packed-FFT unpack, random phase.
// For a KEPT channel: identity spectrum H = X(k) (the original Hermitian
// spectrum), so the inverse FFT reproduces the original series (~1e-7 rel).
__device__ __forceinline__ void rebuild(float2* __restrict__ buf, int ka, int kb,
                                        float2 phA, float2 phB,
                                        bool sA, bool sB) {
    const float TWO_PI = 6.283185307179586476925f;
    const float scale  = 0.25f / (float)FFT_N;
    float2 Za = buf[SWZ(ka)], Zb = buf[SWZ(kb)];
    float ax = Za.x + Zb.x, ay = Za.y - Zb.y;   // 2*X_A(ka)
    float bx = Za.y + Zb.y, by = Zb.x - Za.x;   // 2*X_B(ka)
    float h1x, h1y, h2x, h2y;
    if (sA) {
        float ampA = sqrtf(fmaf(ax, ax, ay * ay)) * scale;
        float sA1, cA1, sA2, cA2;
        __sincosf(TWO_PI * phA.x, &sA1, &cA1);
        __sincosf(TWO_PI * phA.y, &sA2, &cA2);
        h1x = ampA * (cA1 + cA2);  h1y = ampA * (sA1 - sA2);
    } else {
        h1x = ax * (2.0f * scale); h1y = ay * (2.0f * scale);
    }
    if (sB) {
        float ampB = sqrtf(fmaf(bx, bx, by * by)) * scale;
        float sB1, cB1, sB2, cB2;
        __sincosf(TWO_PI * phB.x, &sB1, &cB1);
        __sincosf(TWO_PI * phB.y, &sB2, &cB2);
        h2x = ampB * (cB1 + cB2);  h2y = ampB * (sB1 - sB2);
    } else {
        h2x = bx * (2.0f * scale); h2y = by * (2.0f * scale);
    }
    buf[SWZ(ka)] = make_float2(h1x - h2y, h1y + h2x);
    buf[SWZ(kb)] = make_float2(h1x + h2y, h2x - h1y);
}

__global__ __launch_bounds__(NT, 1)
void surrogate_kernel(const float* __restrict__ wave,
                      const float* __restrict__ phases,
                      const float* __restrict__ mask,
                      float* __restrict__ out) {
    const int blk = blockIdx.x;
    const int b   = blk >> 4;
    const int c0  = (blk & 15) * 4;
    const int tid = threadIdx.x;

    const bool s0 = mask[b * CH + c0]     < 0.5f;
    const bool s1 = mask[b * CH + c0 + 1] < 0.5f;
    const bool s2 = mask[b * CH + c0 + 2] < 0.5f;
    const bool s3 = mask[b * CH + c0 + 3] < 0.5f;
    const bool p0 = s0 | s1;
    const bool p1 = s2 | s3;

    const float4* w4 = (const float4*)(wave   + (size_t)b * FFT_N * CH + c0);
    const float4* p4 = (const float4*)(phases + (size_t)b * FFT_N * CH + c0);
    float4*       o4 = (float4*)      (out    + (size_t)b * FFT_N * CH + c0);

    if (!p0 && !p1) {
        #pragma unroll 4
        for (int t = tid; t < FFT_N; t += NT)
            o4[(size_t)t * 16] = w4[(size_t)t * 16];
        return;
    }

    extern __shared__ float2 sm[];
    float2* b0 = sm;            // pair 0: ch c0 + i*ch(c0+1)
    float2* b1 = sm + FFT_N;    // pair 1: ch c0+2 + i*ch(c0+3)

    // ---- Load: one float4 per time sample -> both buffers -----------------
    #pragma unroll
    for (int i = 0; i < FFT_N / NT; i++) {
        int t = tid + i * NT;
        float4 g = w4[(size_t)t * 16];
        b0[SWZ(t)] = make_float2(g.x, g.y);
        b1[SWZ(t)] = make_float2(g.z, g.w);
    }
    __syncthreads();

    // ---- Forward FFT: radix-16 x3 (halves decoupled) + radix-2 -------------
    stage16_pair<1,   1>(b0, b1, tid, p0, p1);
    stage16_pair<16,  1>(b0, b1, tid, p0, p1);
    stage16_pair<256, 1>(b0, b1, tid, p0, p1);
    __syncthreads();

    #pragma unroll
    for (int i = 0; i < FFT_N / 2 / NT; i++) {
        int j = tid + i * NT;
        float ss, cc;
        sincospif(-(float)j / 4096.0f, &ss, &cc);
        float2 w = make_float2(cc, ss);
        if (p0) {
            float2 u0 = b0[SWZ(j)], u1 = cmul(b0[SWZ(j + 4096)], w);
            b0[SWZ(j)] = cadd(u0, u1);  b0[SWZ(j + 4096)] = csub(u0, u1);
        }
        if (p1) {
            float2 u0 = b1[SWZ(j)], u1 = cmul(b1[SWZ(j + 4096)], w);
            b1[SWZ(j)] = cadd(u0, u1);  b1[SWZ(j + 4096)] = csub(u0, u1);
        }
    }
    __syncthreads();

    // ---- Spectrum rebuild: surrogate lanes get random phases, kept lanes ---
    // get their identity spectrum (IFFT then reproduces the original series).
    for (int k = tid; k <= FFT_N / 2; k += NT) {
        const int nk = (FFT_N - k) & (FFT_N - 1);
        float4 pk  = p4[(size_t)k  * 16];
        float4 pnk = p4[(size_t)nk * 16];
        if (p0) rebuild(b0, k, nk, make_float2(pk.x, pnk.x), make_float2(pk.y, pnk.y), s0, s1);
        if (p1) rebuild(b1, k, nk, make_float2(pk.z, pnk.z), make_float2(pk.w, pnk.w), s2, s3);
    }
    __syncthreads();

    // ---- Inverse FFT: radix-16 x3 (halves decoupled) ------------------------
    stage16_pair<1,   -1>(b0, b1, tid, p0, p1);
    stage16_pair<16,  -1>(b0, b1, tid, p0, p1);
    stage16_pair<256, -1>(b0, b1, tid, p0, p1);
    __syncthreads();

    // ---- Final inverse radix-2 + float4 store (no reload, no select) -------
    #pragma unroll
    for (int i = 0; i < FFT_N / 2 / NT; i++) {
        int j = tid + i * NT;
        float ss, cc;
        sincospif((float)j / 4096.0f, &ss, &cc);
        float2 w = make_float2(cc, ss);
        float2 y0, y1, z0, z1;
        if (p0) {
            float2 u0 = b0[SWZ(j)], u1 = cmul(b0[SWZ(j + 4096)], w);
            y0 = cadd(u0, u1);  y1 = csub(u0, u1);
        } else {   // pair fully kept: b0 still holds the originals (in place)
            y0 = b0[SWZ(j)];  y1 = b0[SWZ(j + 4096)];
        }
        if (p1) {
            float2 u0 = b1[SWZ(j)], u1 = cmul(b1[SWZ(j + 4096)], w);
            z0 = cadd(u0, u1);  z1 = csub(u0, u1);
        } else {
            z0 = b1[SWZ(j)];  z1 = b1[SWZ(j + 4096)];
        }
        o4[(size_t)j * 16]          = make_float4(y0.x, y0.y, z0.x, z0.y);
        o4[(size_t)(j + 4096) * 16] = make_float4(y1.x, y1.y, z1.x, z1.y);
    }
}

extern "C" void kernel_launch(void* const* d_in, const int* in_sizes, int n_in,
                              void* d_out, int out_size) {
    const float* wave   = (const float*)d_in[0];
    const float* phases = (const float*)d_in[1];
    const float* maskp  = (const float*)d_in[2];
    float* out = (float*)d_out;

    const int B = in_sizes[0] / (FFT_N * CH);
    const int smem = 2 * FFT_N * (int)sizeof(float2);   // 131,072 B

    cudaFuncSetAttribute(surrogate_kernel,
                         cudaFuncAttributeMaxDynamicSharedMemorySize, smem);
    surrogate_kernel<<<B * (CH / 4), NT, smem>>>(wave, phases, maskp, out);
}